// round 13
// baseline (speedup 1.0000x reference)
#include <cuda_runtime.h>
#include <cuda_bf16.h>
#include <math.h>
#include <stdint.h>

// Problem constants
#define B_  2
#define S_  2048
#define H_  1024
#define NH_ 16
#define D_  64
#define ROWS_ (B_*S_)        // 4096
#define EPS_ 1.1920929e-07f
#define QSCALE_ (0.125f * 1.4426950408889634f)   // (1/sqrt(D)) * log2(e)

// K-dim permutation within each 8-group: k -> 2*(k&3) + ((k>>2)&1)
// stored order per group: 0,4,1,5,2,6,3,7 (mma pairs (k,k+4) adjacent -> LDS.64 frags)

// ---------------- scratch -------------------------------------------------------------
__device__ float g_qkv[(size_t)ROWS_ * 3 * H_];   // natural (QKV gemm output)
__device__ float g_q[(size_t)B_*NH_*S_*D_];       // d-permuted (flash frag layout)
__device__ float g_k[(size_t)B_*NH_*S_*D_];       // d-permuted
__device__ float g_v[(size_t)B_*NH_*S_*D_];       // natural
__device__ float g_attn[(size_t)ROWS_ * H_];      // h-PERMUTED (K dim of Wo gemm)
__device__ float g_x32[(size_t)ROWS_ * H_];       // tf32 + k-permuted
__device__ float g_w1[(size_t)3*H_ * H_];         // tf32 + k-permuted
__device__ float g_w2[(size_t)H_ * H_];           // tf32 + k-permuted
__device__ float g_cos[S_*32];
__device__ float g_sin[S_*32];

// ---------------- helpers -------------------------------------------------------------
__device__ __forceinline__ unsigned f2tf32(float f) {
    unsigned u;
    asm("cvt.rna.tf32.f32 %0, %1;" : "=r"(u) : "f"(f));
    return u;
}
__device__ __forceinline__ float ex2(float x) {
    float r;
    asm("ex2.approx.f32 %0, %1;" : "=f"(r) : "f"(x));
    return r;
}
__device__ __forceinline__ void mma_tf32(float c[4], const unsigned a[4], const unsigned b[2]) {
    asm volatile(
        "mma.sync.aligned.m16n8k8.row.col.f32.tf32.tf32.f32 "
        "{%0,%1,%2,%3}, {%4,%5,%6,%7}, {%8,%9}, {%0,%1,%2,%3};"
        : "+f"(c[0]), "+f"(c[1]), "+f"(c[2]), "+f"(c[3])
        : "r"(a[0]), "r"(a[1]), "r"(a[2]), "r"(a[3]), "r"(b[0]), "r"(b[1]));
}
__device__ __forceinline__ void cp16(unsigned dst, const void* src) {
    asm volatile("cp.async.cg.shared.global [%0], [%1], 16;" :: "r"(dst), "l"(src));
}
__device__ __forceinline__ uint32_t smem_u32(const void* p) {
    return (uint32_t)__cvta_generic_to_shared(p);
}

// ---------------- tf32 rounding + k-pair permutation (8 elems / thread) ---------------
__global__ void cvt_tf32_perm_kernel(const float* __restrict__ in, float* __restrict__ out,
                                     int n) {
    int i = (blockIdx.x * blockDim.x + threadIdx.x) * 8;
    if (i >= n) return;
    float4 v0 = *(const float4*)(in + i);
    float4 v1 = *(const float4*)(in + i + 4);
    float4 o0, o1;   // order: k0,k4,k1,k5 | k2,k6,k3,k7
    o0.x = __uint_as_float(f2tf32(v0.x));
    o0.y = __uint_as_float(f2tf32(v1.x));
    o0.z = __uint_as_float(f2tf32(v0.y));
    o0.w = __uint_as_float(f2tf32(v1.y));
    o1.x = __uint_as_float(f2tf32(v0.z));
    o1.y = __uint_as_float(f2tf32(v1.z));
    o1.z = __uint_as_float(f2tf32(v0.w));
    o1.w = __uint_as_float(f2tf32(v1.w));
    *(float4*)(out + i)     = o0;
    *(float4*)(out + i + 4) = o1;
}

// ---------------- RoPE table ----------------------------------------------------------
__global__ void rope_table_kernel() {
    int idx = blockIdx.x * blockDim.x + threadIdx.x;
    if (idx >= S_*32) return;
    int s = idx >> 5, j = idx & 31;
    double invf = pow(1.0e-4, (double)j / 32.0);
    float f = (float)s * (float)invf;
    double sn, cs;
    sincos((double)f, &sn, &cs);
    g_cos[idx] = (float)cs;
    g_sin[idx] = (float)sn;
}

// ---------------- tf32 GEMM v9: v8 pipeline + uint2 frags from k-permuted gmem --------
// Per slab t (3 stages, 1 barrier): load(t+1) -> wait_group 1 -> barrier -> compute.
// Frag loads: kb = ks*8 + 2*gc reads the (k, k+4) pair as one LDS.64.
// Per ks-step: 4 a-uint2 + 8 b-uint2 = 12 LDS.64 (was 24 LDS.32). Loader UNCHANGED.
#define GP 36
#define GSLAB (128*GP)
#define GEMM_SMEM_BYTES (6*GSLAB*4)            // 110592 -> 2 CTAs/SM

__global__ __launch_bounds__(256, 2)
void gemm_v9(const float* __restrict__ A, const float* __restrict__ Bm,
             float* __restrict__ C, int M, int N, int K) {
    extern __shared__ unsigned smg[];
    unsigned* As = smg;                        // [3][128][GP]
    unsigned* Bs = smg + 3*GSLAB;

    const int tid  = threadIdx.x;
    const int lane = tid & 31;
    const int wid  = tid >> 5;
    const int gr   = lane >> 2;
    const int gc   = lane & 3;
    const int bm = blockIdx.y * 128;
    const int bn = blockIdx.x * 128;
    const int wm = (wid >> 1) * 32;
    const int wn = (wid & 1) * 64;

    const int lr = tid >> 2;                   // 0..63
    const int lc = (tid & 3) << 2;             // 0,4,8,12
    const unsigned as_u32 = smem_u32(As);
    const unsigned bs_u32 = smem_u32(Bs);

    auto load_slab = [&](int t, int s) {
        const int k0 = t << 5;
        const unsigned ad = as_u32 + (unsigned)(s*GSLAB*4);
        const unsigned bd = bs_u32 + (unsigned)(s*GSLAB*4);
#pragma unroll
        for (int rr = 0; rr < 2; rr++) {
            int r = lr + rr*64;
#pragma unroll
            for (int cc = 0; cc < 2; cc++) {
                int c = lc + cc*16;
                unsigned off = (unsigned)((r*GP + c) * 4);
                cp16(ad + off, A  + (size_t)(bm + r) * K + k0 + c);
                cp16(bd + off, Bm + (size_t)(bn + r) * K + k0 + c);
            }
        }
        asm volatile("cp.async.commit_group;");
    };

    float acc[2][8][4];
#pragma unroll
    for (int mi = 0; mi < 2; mi++)
#pragma unroll
        for (int ni = 0; ni < 8; ni++)
#pragma unroll
            for (int j = 0; j < 4; j++) acc[mi][ni][j] = 0.f;

    const int T = K >> 5;                      // 32 slabs
    load_slab(0, 0);

    for (int t = 0; t < T; t++) {
        const int cur = t % 3;
        if (t + 1 < T) {
            load_slab(t + 1, (t + 1) % 3);
            asm volatile("cp.async.wait_group 1;");
        } else {
            asm volatile("cp.async.wait_group 0;");
        }
        __syncthreads();

        const unsigned* Ab = As + cur*GSLAB;
        const unsigned* Bb = Bs + cur*GSLAB;
#pragma unroll
        for (int ks = 0; ks < 4; ks++) {
            const int kb = ks*8 + 2*gc;        // permuted pair base
            unsigned a[2][4];
#pragma unroll
            for (int mi = 0; mi < 2; mi++) {
                uint2 lo = *(const uint2*)&Ab[(wm + mi*16 + gr)*GP + kb];
                uint2 hi = *(const uint2*)&Ab[(wm + mi*16 + 8 + gr)*GP + kb];
                a[mi][0] = lo.x; a[mi][1] = hi.x; a[mi][2] = lo.y; a[mi][3] = hi.y;
            }
#pragma unroll
            for (int ni = 0; ni < 8; ni++) {
                uint2 bb = *(const uint2*)&Bb[(wn + ni*8 + gr)*GP + kb];
                unsigned b[2] = { bb.x, bb.y };
                mma_tf32(acc[0][ni], a[0], b);
                mma_tf32(acc[1][ni], a[1], b);
            }
        }
    }

#pragma unroll
    for (int mi = 0; mi < 2; mi++) {
        int m0 = bm + wm + mi*16 + gr;
#pragma unroll
        for (int ni = 0; ni < 8; ni++) {
            int n = bn + wn + ni*8 + 2*gc;
            *(float2*)(C + (size_t)m0 * N + n)       = make_float2(acc[mi][ni][0], acc[mi][ni][1]);
            *(float2*)(C + (size_t)(m0 + 8) * N + n) = make_float2(acc[mi][ni][2], acc[mi][ni][3]);
        }
    }
}

// ---------------- prep: RMSNorm+RoPE, lambda-mix; q/k stored d-permuted ---------------
// (reads natural g_qkv; QKV gemm output is natural since permutation is over summed K)
__global__ void prep_kernel(const float* __restrict__ ve, const float* __restrict__ lambdas) {
    int gtid = blockIdx.x * blockDim.x + threadIdx.x;
    int warp = gtid >> 5;
    int lane = gtid & 31;
    if (warp >= B_*S_*NH_) return;
    int h = warp % NH_;
    int s = (warp / NH_) % S_;
    int b = warp / (NH_ * S_);

    const float* row = g_qkv + (size_t)(b*S_ + s) * (3*H_);
    float q1 = row[h*64 + lane],          q2 = row[h*64 + 32 + lane];
    float k1 = row[H_ + h*64 + lane],     k2 = row[H_ + h*64 + 32 + lane];
    float v1 = row[2*H_ + h*64 + lane],   v2 = row[2*H_ + h*64 + 32 + lane];

    float sq = q1*q1 + q2*q2;
    float sk = k1*k1 + k2*k2;
#pragma unroll
    for (int o = 16; o; o >>= 1) {
        sq += __shfl_xor_sync(0xffffffffu, sq, o);
        sk += __shfl_xor_sync(0xffffffffu, sk, o);
    }
    float rq = rsqrtf(sq * (1.f/64.f) + EPS_);
    float rk = rsqrtf(sk * (1.f/64.f) + EPS_);
    q1 *= rq; q2 *= rq; k1 *= rk; k2 *= rk;

    float c  = g_cos[s*32 + lane];
    float sn = g_sin[s*32 + lane];
    float qo1 = (q1*c + q2*sn) * QSCALE_;
    float qo2 = (q2*c - q1*sn) * QSCALE_;
    float ko1 = k1*c + k2*sn, ko2 = k2*c - k1*sn;

    float l0 = lambdas[0], l1 = lambdas[1];
    const float* verow = ve + (size_t)(b*S_ + s) * H_ + h*64;
    float vo1 = l0*v1 + l1*verow[lane];
    float vo2 = l0*v2 + l1*verow[32 + lane];

    size_t ob = ((size_t)(b*NH_ + h) * S_ + s) * 64;
    int j    = lane & 7;
    int pbase = (lane >> 3) * 8 + 2*(j & 3) + (j >> 2);
    g_q[ob + pbase]      = __uint_as_float(f2tf32(qo1));
    g_q[ob + pbase + 32] = __uint_as_float(f2tf32(qo2));
    g_k[ob + pbase]      = __uint_as_float(f2tf32(ko1));
    g_k[ob + pbase + 32] = __uint_as_float(f2tf32(ko2));
    g_v[ob + lane]       = __uint_as_float(f2tf32(vo1));
    g_v[ob + lane + 32]  = __uint_as_float(f2tf32(vo2));
}

// ---------------- flash attention v7: v6 + h-permuted g_attn store --------------------
#define FSTR 72
#define STAGE_W (64*FSTR)
#define FLASH_SMEM_BYTES ((128*FSTR + 4*STAGE_W)*4)   // 110592

__global__ __launch_bounds__(256, 2)
void flash_v7() {
    extern __shared__ float sm[];
    float* QP = sm;
    float* Ks = sm + 128*FSTR;
    float* Vs = Ks + 2*STAGE_W;

    const int tid  = threadIdx.x;
    const int lane = tid & 31;
    const int wid  = tid >> 5;
    const int gr   = lane >> 2;
    const int gc   = lane & 3;
    const int qt   = gridDim.x - 1 - blockIdx.x;
    const int bh   = blockIdx.y;
    const int arow = wid*16 + gr;

    const unsigned ks_u32 = smem_u32(Ks);
    const unsigned vs_u32 = smem_u32(Vs);
    const float* Kbase = g_k + (size_t)bh * S_ * 64;
    const float* Vbase = g_v + (size_t)bh * S_ * 64;
    const int ktmax = 2*qt + 1;

    const int cr = tid >> 4;
    const int cc = (tid & 15) << 2;

    {
#pragma unroll
        for (int j = 0; j < 4; j++) {
            int r = cr + j*16;
            unsigned off = (unsigned)((r*FSTR + cc) * 4);
            cp16(ks_u32 + off, Kbase + r*64 + cc);
            cp16(vs_u32 + off, Vbase + r*64 + cc);
        }
        asm volatile("cp.async.commit_group;");
    }

    const float* Qg = g_q + ((size_t)bh * S_ + qt*128) * 64;
    for (int i = tid; i < 2048; i += 256) {
        int r = i >> 4, dc = (i & 15) << 2;
        *(float4*)&QP[r*FSTR + dc] = *(const float4*)(Qg + r*64 + dc);
    }
    __syncthreads();

    unsigned qa[8][4];
#pragma unroll
    for (int ks = 0; ks < 8; ks++) {
        uint2 lo = *(const uint2*)&QP[arow*FSTR + ks*8 + 2*gc];
        uint2 hi = *(const uint2*)&QP[(arow+8)*FSTR + ks*8 + 2*gc];
        qa[ks][0] = lo.x; qa[ks][1] = hi.x; qa[ks][2] = lo.y; qa[ks][3] = hi.y;
    }

    float o[8][4];
#pragma unroll
    for (int ni = 0; ni < 8; ni++)
#pragma unroll
        for (int j = 0; j < 4; j++) o[ni][j] = 0.f;
    float m0 = -INFINITY, m1 = -INFINITY, l0 = 0.f, l1 = 0.f;

    for (int kt = 0; kt <= ktmax; kt++) {
        const int cur = kt & 1;
        __syncthreads();

        if (kt < ktmax) {
            const int nst = cur ^ 1;
            const float* Kg = Kbase + (size_t)(kt+1)*64*64;
            const float* Vg = Vbase + (size_t)(kt+1)*64*64;
            unsigned kd = ks_u32 + (unsigned)(nst*STAGE_W*4);
            unsigned vd = vs_u32 + (unsigned)(nst*STAGE_W*4);
#pragma unroll
            for (int j = 0; j < 4; j++) {
                int r = cr + j*16;
                unsigned off = (unsigned)((r*FSTR + cc) * 4);
                cp16(kd + off, Kg + r*64 + cc);
                cp16(vd + off, Vg + r*64 + cc);
            }
            asm volatile("cp.async.commit_group;");
            asm volatile("cp.async.wait_group 1;");
        } else {
            asm volatile("cp.async.wait_group 0;");
        }
        __syncthreads();

        const float* Kst = Ks + cur*STAGE_W;
        const float* Vst = Vs + cur*STAGE_W;

        float sc[8][4];
#pragma unroll
        for (int ni = 0; ni < 8; ni++)
#pragma unroll
            for (int j = 0; j < 4; j++) sc[ni][j] = 0.f;
#pragma unroll
        for (int ks = 0; ks < 8; ks++) {
#pragma unroll
            for (int ni = 0; ni < 8; ni++) {
                uint2 bb = *(const uint2*)&Kst[(ni*8 + gr)*FSTR + ks*8 + 2*gc];
                unsigned b[2] = { bb.x, bb.y };
                mma_tf32(sc[ni], qa[ks], b);
            }
        }

        const int qrow0 = qt*128 + wid*16 + gr;
        if (kt >= 2*qt) {
#pragma unroll
            for (int ni = 0; ni < 8; ni++) {
                int col = kt*64 + ni*8 + 2*gc;
                if (col     > qrow0)     sc[ni][0] = -1e30f;
                if (col + 1 > qrow0)     sc[ni][1] = -1e30f;
                if (col     > qrow0 + 8) sc[ni][2] = -1e30f;
                if (col + 1 > qrow0 + 8) sc[ni][3] = -1e30f;
            }
        }

        float mx0 = -INFINITY, mx1 = -INFINITY;
#pragma unroll
        for (int ni = 0; ni < 8; ni++) {
            mx0 = fmaxf(mx0, fmaxf(sc[ni][0], sc[ni][1]));
            mx1 = fmaxf(mx1, fmaxf(sc[ni][2], sc[ni][3]));
        }
        mx0 = fmaxf(mx0, __shfl_xor_sync(0xffffffffu, mx0, 1));
        mx0 = fmaxf(mx0, __shfl_xor_sync(0xffffffffu, mx0, 2));
        mx1 = fmaxf(mx1, __shfl_xor_sync(0xffffffffu, mx1, 1));
        mx1 = fmaxf(mx1, __shfl_xor_sync(0xffffffffu, mx1, 2));
        float mn0 = fmaxf(m0, mx0), mn1 = fmaxf(m1, mx1);
        float al0 = ex2(m0 - mn0), al1 = ex2(m1 - mn1);
        m0 = mn0; m1 = mn1;

        const int pp = (gc < 2) ? 4*gc : 4*gc - 7;
        float* pr0 = &QP[arow*FSTR];
        float* pr1 = &QP[(arow+8)*FSTR];
        float s0 = 0.f, s1 = 0.f;
#pragma unroll
        for (int ni = 0; ni < 8; ni++) {
            float p00 = ex2(sc[ni][0] - mn0);
            float p01 = ex2(sc[ni][1] - mn0);
            float p10 = ex2(sc[ni][2] - mn1);
            float p11 = ex2(sc[ni][3] - mn1);
            s0 += p00 + p01;
            s1 += p10 + p11;
            int c = ni*8 + pp;
            pr0[c]   = p00;  pr0[c+2] = p01;
            pr1[c]   = p10;  pr1[c+2] = p11;
        }
        s0 += __shfl_xor_sync(0xffffffffu, s0, 1);
        s0 += __shfl_xor_sync(0xffffffffu, s0, 2);
        s1 += __shfl_xor_sync(0xffffffffu, s1, 1);
        s1 += __shfl_xor_sync(0xffffffffu, s1, 2);
        l0 = l0 * al0 + s0;
        l1 = l1 * al1 + s1;

#pragma unroll
        for (int ni = 0; ni < 8; ni++) {
            o[ni][0] *= al0; o[ni][1] *= al0;
            o[ni][2] *= al1; o[ni][3] *= al1;
        }
        __syncwarp();

#pragma unroll
        for (int ks = 0; ks < 8; ks++) {
            uint2 plo = *(const uint2*)&QP[arow*FSTR + ks*8 + 2*gc];
            uint2 phi = *(const uint2*)&QP[(arow+8)*FSTR + ks*8 + 2*gc];
            unsigned pa[4] = { plo.x, phi.x, plo.y, phi.y };
#pragma unroll
            for (int ni = 0; ni < 8; ni++) {
                unsigned b[2] = { __float_as_uint(Vst[(ks*8 + gc)*FSTR + ni*8 + gr]),
                                  __float_as_uint(Vst[(ks*8 + gc + 4)*FSTR + ni*8 + gr]) };
                mma_tf32(o[ni], pa, b);
            }
        }
    }

    float inv0 = 1.f / l0, inv1 = 1.f / l1;
    const int b = bh / NH_, h = bh % NH_;
    const int srow0 = qt*128 + wid*16 + gr;
    const int pp = (gc < 2) ? 4*gc : 4*gc - 7;
#pragma unroll
    for (int ni = 0; ni < 8; ni++) {
        int colb = h*64 + ni*8;
        float* d0 = g_attn + (size_t)(b*S_ + srow0) * H_ + colb;
        float* d1 = g_attn + (size_t)(b*S_ + srow0 + 8) * H_ + colb;
        // h-permuted store: natural cols (c, c+1) land at (pp, pp+2) within the 8-group
        d0[pp]   = __uint_as_float(f2tf32(o[ni][0]*inv0));
        d0[pp+2] = __uint_as_float(f2tf32(o[ni][1]*inv0));
        d1[pp]   = __uint_as_float(f2tf32(o[ni][2]*inv1));
        d1[pp+2] = __uint_as_float(f2tf32(o[ni][3]*inv1));
    }
}

// ---------------- launch --------------------------------------------------------------
extern "C" void kernel_launch(void* const* d_in, const int* in_sizes, int n_in,
                              void* d_out, int out_size) {
    (void)in_sizes; (void)n_in; (void)out_size;
    const float* x       = (const float*)d_in[0];
    const float* ve      = (const float*)d_in[1];
    const float* Wqkv    = (const float*)d_in[2];
    const float* Wo      = (const float*)d_in[3];
    const float* lambdas = (const float*)d_in[4];
    float* out = (float*)d_out;

    void *p_qkv, *p_attn, *p_x32, *p_w1, *p_w2;
    cudaGetSymbolAddress(&p_qkv,  g_qkv);
    cudaGetSymbolAddress(&p_attn, g_attn);
    cudaGetSymbolAddress(&p_x32,  g_x32);
    cudaGetSymbolAddress(&p_w1,   g_w1);
    cudaGetSymbolAddress(&p_w2,   g_w2);

    static bool attr_done = false;
    if (!attr_done) {
        cudaFuncSetAttribute(flash_v7, cudaFuncAttributeMaxDynamicSharedMemorySize,
                             FLASH_SMEM_BYTES);
        cudaFuncSetAttribute(gemm_v9, cudaFuncAttributeMaxDynamicSharedMemorySize,
                             GEMM_SMEM_BYTES);
        attr_done = true;
    }

    // 0) tf32-round + k-permute GEMM inputs
    cvt_tf32_perm_kernel<<<ROWS_*H_/8/256, 256>>>(x,    (float*)p_x32, ROWS_*H_);
    cvt_tf32_perm_kernel<<<3*H_*H_/8/256,  256>>>(Wqkv, (float*)p_w1,  3*H_*H_);
    cvt_tf32_perm_kernel<<<H_*H_/8/256,    256>>>(Wo,   (float*)p_w2,  H_*H_);
    // 1) qkv = x @ W_qkv^T   (output natural)
    gemm_v9<<<dim3(3*H_/128, ROWS_/128), 256, GEMM_SMEM_BYTES>>>(
        (const float*)p_x32, (const float*)p_w1, (float*)p_qkv, ROWS_, 3*H_, H_);
    // 2) RoPE table
    rope_table_kernel<<<(S_*32 + 255)/256, 256>>>();
    // 3) prep
    prep_kernel<<<(B_*S_*NH_*32 + 255)/256, 256>>>(ve, lambdas);
    // 4) causal flash attention (writes g_attn h-permuted)
    flash_v7<<<dim3(S_/128, B_*NH_), 256, FLASH_SMEM_BYTES>>>();
    // 5) out = attn @ W_o^T  (both operands k-permuted consistently; output natural)
    gemm_v9<<<dim3(H_/128, ROWS_/128), 256, GEMM_SMEM_BYTES>>>(
        (const float*)p_attn, (const float*)p_w2, out, ROWS_, H_, H_);
}

// round 14
// speedup vs baseline: 1.1244x; 1.1244x over previous
#include <cuda_runtime.h>
#include <cuda_bf16.h>
#include <math.h>
#include <stdint.h>

// Problem constants
#define B_  2
#define S_  2048
#define H_  1024
#define NH_ 16
#define D_  64
#define ROWS_ (B_*S_)        // 4096
#define EPS_ 1.1920929e-07f
#define QSCALE_ (0.125f * 1.4426950408889634f)   // (1/sqrt(D)) * log2(e)

// ---------------- scratch -------------------------------------------------------------
__device__ float g_qkv[(size_t)ROWS_ * 3 * H_];   // natural
__device__ float g_q[(size_t)B_*NH_*S_*D_];       // d-permuted (flash frag layout)
__device__ float g_k[(size_t)B_*NH_*S_*D_];       // d-permuted
__device__ float g_v[(size_t)B_*NH_*S_*D_];       // natural [bh][s][d]
__device__ float g_vt[(size_t)B_*NH_*D_*S_];      // transposed [bh][d][s-permuted]
__device__ float g_attn[(size_t)ROWS_ * H_];      // natural, tf32-rounded
__device__ float g_x32[(size_t)ROWS_ * H_];       // tf32 natural
__device__ float g_w1[(size_t)3*H_ * H_];         // tf32 natural
__device__ float g_w2[(size_t)H_ * H_];           // tf32 natural
__device__ float g_cos[S_*32];
__device__ float g_sin[S_*32];

// ---------------- helpers -------------------------------------------------------------
__device__ __forceinline__ unsigned f2tf32(float f) {
    unsigned u;
    asm("cvt.rna.tf32.f32 %0, %1;" : "=r"(u) : "f"(f));
    return u;
}
__device__ __forceinline__ float ex2(float x) {
    float r;
    asm("ex2.approx.f32 %0, %1;" : "=f"(r) : "f"(x));
    return r;
}
__device__ __forceinline__ void mma_tf32(float c[4], const unsigned a[4], const unsigned b[2]) {
    asm volatile(
        "mma.sync.aligned.m16n8k8.row.col.f32.tf32.tf32.f32 "
        "{%0,%1,%2,%3}, {%4,%5,%6,%7}, {%8,%9}, {%0,%1,%2,%3};"
        : "+f"(c[0]), "+f"(c[1]), "+f"(c[2]), "+f"(c[3])
        : "r"(a[0]), "r"(a[1]), "r"(a[2]), "r"(a[3]), "r"(b[0]), "r"(b[1]));
}
__device__ __forceinline__ void cp16(unsigned dst, const void* src) {
    asm volatile("cp.async.cg.shared.global [%0], [%1], 16;" :: "r"(dst), "l"(src));
}
__device__ __forceinline__ uint32_t smem_u32(const void* p) {
    return (uint32_t)__cvta_generic_to_shared(p);
}

// ---------------- elementwise tf32 rounding (natural layout) --------------------------
__global__ void cvt_tf32_kernel(const float* __restrict__ in, float* __restrict__ out, int n) {
    int i = (blockIdx.x * blockDim.x + threadIdx.x) * 4;
    if (i >= n) return;
    float4 v = *(const float4*)(in + i);
    float4 o;
    o.x = __uint_as_float(f2tf32(v.x));
    o.y = __uint_as_float(f2tf32(v.y));
    o.z = __uint_as_float(f2tf32(v.z));
    o.w = __uint_as_float(f2tf32(v.w));
    *(float4*)(out + i) = o;
}

// ---------------- RoPE table ----------------------------------------------------------
__global__ void rope_table_kernel() {
    int idx = blockIdx.x * blockDim.x + threadIdx.x;
    if (idx >= S_*32) return;
    int s = idx >> 5, j = idx & 31;
    double invf = pow(1.0e-4, (double)j / 32.0);
    float f = (float)s * (float)invf;
    double sn, cs;
    sincos((double)f, &sn, &cs);
    g_cos[idx] = (float)cs;
    g_sin[idx] = (float)sn;
}

// ---------------- V transpose: g_v [bh][s][d] -> g_vt [bh][d][s-permuted] -------------
// s permuted per 8-group in stored order 0,4,1,5,2,6,3,7 (position p holds
// s_local = (p&1)*4 + ((p>>1)&3)).
__global__ void vtrans_kernel() {
    __shared__ float t[64][68];
    const int bh = blockIdx.y;
    const int st = blockIdx.x;
    const int tid = threadIdx.x;                 // 256
    const float* src = g_v + ((size_t)bh * S_ + st*64) * 64;
    for (int i = tid; i < 1024; i += 256) {      // 64x64 tile, float4 loads
        int r = i >> 4, c = (i & 15) << 2;
        float4 v = *(const float4*)(src + r*64 + c);
        t[r][c] = v.x; t[r][c+1] = v.y; t[r][c+2] = v.z; t[r][c+3] = v.w;
    }
    __syncthreads();
    const int d   = tid >> 2;
    const int ps0 = (tid & 3) * 16;
    float* dst = g_vt + ((size_t)bh * 64 + d) * S_ + st*64 + ps0;
#pragma unroll
    for (int q = 0; q < 16; q += 4) {
        float4 o;
#pragma unroll
        for (int e = 0; e < 4; e++) {
            int ps = ps0 + q + e;
            int sl = (ps & ~7) + ((ps & 1) * 4) + ((ps >> 1) & 3);
            ((float*)&o)[e] = t[sl][d];
        }
        *(float4*)(dst + q) = o;
    }
}

// ---------------- tf32 GEMM v8 (R12 winner, unchanged) --------------------------------
#define GP 36
#define GSLAB (128*GP)
#define GEMM_SMEM_BYTES (6*GSLAB*4)            // 110592 -> 2 CTAs/SM

__global__ __launch_bounds__(256, 2)
void gemm_v8(const float* __restrict__ A, const float* __restrict__ Bm,
             float* __restrict__ C, int M, int N, int K) {
    extern __shared__ unsigned smg[];
    unsigned* As = smg;                        // [3][128][GP]
    unsigned* Bs = smg + 3*GSLAB;

    const int tid  = threadIdx.x;
    const int lane = tid & 31;
    const int wid  = tid >> 5;
    const int gr   = lane >> 2;
    const int gc   = lane & 3;
    const int bm = blockIdx.y * 128;
    const int bn = blockIdx.x * 128;
    const int wm = (wid >> 1) * 32;
    const int wn = (wid & 1) * 64;

    const int lr = tid >> 2;
    const int lc = (tid & 3) << 2;
    const unsigned as_u32 = smem_u32(As);
    const unsigned bs_u32 = smem_u32(Bs);

    auto load_slab = [&](int t, int s) {
        const int k0 = t << 5;
        const unsigned ad = as_u32 + (unsigned)(s*GSLAB*4);
        const unsigned bd = bs_u32 + (unsigned)(s*GSLAB*4);
#pragma unroll
        for (int rr = 0; rr < 2; rr++) {
            int r = lr + rr*64;
#pragma unroll
            for (int cc = 0; cc < 2; cc++) {
                int c = lc + cc*16;
                unsigned off = (unsigned)((r*GP + c) * 4);
                cp16(ad + off, A  + (size_t)(bm + r) * K + k0 + c);
                cp16(bd + off, Bm + (size_t)(bn + r) * K + k0 + c);
            }
        }
        asm volatile("cp.async.commit_group;");
    };

    float acc[2][8][4];
#pragma unroll
    for (int mi = 0; mi < 2; mi++)
#pragma unroll
        for (int ni = 0; ni < 8; ni++)
#pragma unroll
            for (int j = 0; j < 4; j++) acc[mi][ni][j] = 0.f;

    const int T = K >> 5;
    load_slab(0, 0);

    for (int t = 0; t < T; t++) {
        const int cur = t % 3;
        if (t + 1 < T) {
            load_slab(t + 1, (t + 1) % 3);
            asm volatile("cp.async.wait_group 1;");
        } else {
            asm volatile("cp.async.wait_group 0;");
        }
        __syncthreads();

        const unsigned* Ab = As + cur*GSLAB;
        const unsigned* Bb = Bs + cur*GSLAB;
#pragma unroll
        for (int ks = 0; ks < 4; ks++) {
            const int kb = ks * 8;
            unsigned a[2][4];
#pragma unroll
            for (int mi = 0; mi < 2; mi++) {
                const unsigned* ap = &Ab[(wm + mi*16 + gr)*GP + kb + gc];
                a[mi][0] = ap[0];
                a[mi][1] = ap[8*GP];
                a[mi][2] = ap[4];
                a[mi][3] = ap[8*GP + 4];
            }
#pragma unroll
            for (int ni = 0; ni < 8; ni++) {
                const unsigned* bp = &Bb[(wn + ni*8 + gr)*GP + kb + gc];
                unsigned b[2] = { bp[0], bp[4] };
                mma_tf32(acc[0][ni], a[0], b);
                mma_tf32(acc[1][ni], a[1], b);
            }
        }
    }

#pragma unroll
    for (int mi = 0; mi < 2; mi++) {
        int m0 = bm + wm + mi*16 + gr;
#pragma unroll
        for (int ni = 0; ni < 8; ni++) {
            int n = bn + wn + ni*8 + 2*gc;
            *(float2*)(C + (size_t)m0 * N + n)       = make_float2(acc[mi][ni][0], acc[mi][ni][1]);
            *(float2*)(C + (size_t)(m0 + 8) * N + n) = make_float2(acc[mi][ni][2], acc[mi][ni][3]);
        }
    }
}

// ---------------- prep (unchanged from R12) -------------------------------------------
__global__ void prep_kernel(const float* __restrict__ ve, const float* __restrict__ lambdas) {
    int gtid = blockIdx.x * blockDim.x + threadIdx.x;
    int warp = gtid >> 5;
    int lane = gtid & 31;
    if (warp >= B_*S_*NH_) return;
    int h = warp % NH_;
    int s = (warp / NH_) % S_;
    int b = warp / (NH_ * S_);

    const float* row = g_qkv + (size_t)(b*S_ + s) * (3*H_);
    float q1 = row[h*64 + lane],          q2 = row[h*64 + 32 + lane];
    float k1 = row[H_ + h*64 + lane],     k2 = row[H_ + h*64 + 32 + lane];
    float v1 = row[2*H_ + h*64 + lane],   v2 = row[2*H_ + h*64 + 32 + lane];

    float sq = q1*q1 + q2*q2;
    float sk = k1*k1 + k2*k2;
#pragma unroll
    for (int o = 16; o; o >>= 1) {
        sq += __shfl_xor_sync(0xffffffffu, sq, o);
        sk += __shfl_xor_sync(0xffffffffu, sk, o);
    }
    float rq = rsqrtf(sq * (1.f/64.f) + EPS_);
    float rk = rsqrtf(sk * (1.f/64.f) + EPS_);
    q1 *= rq; q2 *= rq; k1 *= rk; k2 *= rk;

    float c  = g_cos[s*32 + lane];
    float sn = g_sin[s*32 + lane];
    float qo1 = (q1*c + q2*sn) * QSCALE_;
    float qo2 = (q2*c - q1*sn) * QSCALE_;
    float ko1 = k1*c + k2*sn, ko2 = k2*c - k1*sn;

    float l0 = lambdas[0], l1 = lambdas[1];
    const float* verow = ve + (size_t)(b*S_ + s) * H_ + h*64;
    float vo1 = l0*v1 + l1*verow[lane];
    float vo2 = l0*v2 + l1*verow[32 + lane];

    size_t ob = ((size_t)(b*NH_ + h) * S_ + s) * 64;
    int j    = lane & 7;
    int pbase = (lane >> 3) * 8 + 2*(j & 3) + (j >> 2);
    g_q[ob + pbase]      = __uint_as_float(f2tf32(qo1));
    g_q[ob + pbase + 32] = __uint_as_float(f2tf32(qo2));
    g_k[ob + pbase]      = __uint_as_float(f2tf32(ko1));
    g_k[ob + pbase + 32] = __uint_as_float(f2tf32(ko2));
    g_v[ob + lane]       = __uint_as_float(f2tf32(vo1));
    g_v[ob + lane + 32]  = __uint_as_float(f2tf32(vo2));
}

// ---------------- flash attention v8: v6 + transposed V (uint2 PV b-frags) ------------
#define FSTR 72
#define STAGE_W (64*FSTR)
#define FLASH_SMEM_BYTES ((128*FSTR + 4*STAGE_W)*4)   // 110592

__global__ __launch_bounds__(256, 2)
void flash_v8() {
    extern __shared__ float sm[];
    float* QP = sm;                    // 128 x 72 (Q d-permuted; later P n-permuted)
    float* Ks = sm + 128*FSTR;         // 2 x 64 x 72 (K d-permuted, row = n)
    float* Vs = Ks + 2*STAGE_W;        // 2 x 64 x 72 (V TRANSPOSED: row = d, col = s-perm)

    const int tid  = threadIdx.x;
    const int lane = tid & 31;
    const int wid  = tid >> 5;
    const int gr   = lane >> 2;
    const int gc   = lane & 3;
    const int qt   = gridDim.x - 1 - blockIdx.x;
    const int bh   = blockIdx.y;
    const int arow = wid*16 + gr;

    const unsigned ks_u32 = smem_u32(Ks);
    const unsigned vs_u32 = smem_u32(Vs);
    const float* Kbase  = g_k  + (size_t)bh * S_ * 64;
    const float* Vtbase = g_vt + (size_t)bh * 64 * S_;
    const int ktmax = 2*qt + 1;

    const int cr = tid >> 4;
    const int cc = (tid & 15) << 2;

    {
#pragma unroll
        for (int j = 0; j < 4; j++) {
            int r = cr + j*16;
            unsigned off = (unsigned)((r*FSTR + cc) * 4);
            cp16(ks_u32 + off, Kbase + r*64 + cc);
            cp16(vs_u32 + off, Vtbase + (size_t)r*S_ + cc);   // row r = d, tile kt=0
        }
        asm volatile("cp.async.commit_group;");
    }

    const float* Qg = g_q + ((size_t)bh * S_ + qt*128) * 64;
    for (int i = tid; i < 2048; i += 256) {
        int r = i >> 4, dc = (i & 15) << 2;
        *(float4*)&QP[r*FSTR + dc] = *(const float4*)(Qg + r*64 + dc);
    }
    __syncthreads();

    unsigned qa[8][4];
#pragma unroll
    for (int ks = 0; ks < 8; ks++) {
        uint2 lo = *(const uint2*)&QP[arow*FSTR + ks*8 + 2*gc];
        uint2 hi = *(const uint2*)&QP[(arow+8)*FSTR + ks*8 + 2*gc];
        qa[ks][0] = lo.x; qa[ks][1] = hi.x; qa[ks][2] = lo.y; qa[ks][3] = hi.y;
    }

    float o[8][4];
#pragma unroll
    for (int ni = 0; ni < 8; ni++)
#pragma unroll
        for (int j = 0; j < 4; j++) o[ni][j] = 0.f;
    float m0 = -INFINITY, m1 = -INFINITY, l0 = 0.f, l1 = 0.f;

    for (int kt = 0; kt <= ktmax; kt++) {
        const int cur = kt & 1;
        __syncthreads();

        if (kt < ktmax) {
            const int nst = cur ^ 1;
            const float* Kg  = Kbase  + (size_t)(kt+1)*64*64;
            const float* Vtg = Vtbase + (kt+1)*64;           // s-offset within rows
            unsigned kd = ks_u32 + (unsigned)(nst*STAGE_W*4);
            unsigned vd = vs_u32 + (unsigned)(nst*STAGE_W*4);
#pragma unroll
            for (int j = 0; j < 4; j++) {
                int r = cr + j*16;
                unsigned off = (unsigned)((r*FSTR + cc) * 4);
                cp16(kd + off, Kg + r*64 + cc);
                cp16(vd + off, Vtg + (size_t)r*S_ + cc);
            }
            asm volatile("cp.async.commit_group;");
            asm volatile("cp.async.wait_group 1;");
        } else {
            asm volatile("cp.async.wait_group 0;");
        }
        __syncthreads();

        const float* Kst = Ks + cur*STAGE_W;
        const float* Vst = Vs + cur*STAGE_W;

        float sc[8][4];
#pragma unroll
        for (int ni = 0; ni < 8; ni++)
#pragma unroll
            for (int j = 0; j < 4; j++) sc[ni][j] = 0.f;
#pragma unroll
        for (int ks = 0; ks < 8; ks++) {
#pragma unroll
            for (int ni = 0; ni < 8; ni++) {
                uint2 bb = *(const uint2*)&Kst[(ni*8 + gr)*FSTR + ks*8 + 2*gc];
                unsigned b[2] = { bb.x, bb.y };
                mma_tf32(sc[ni], qa[ks], b);
            }
        }

        const int qrow0 = qt*128 + wid*16 + gr;
        if (kt >= 2*qt) {
#pragma unroll
            for (int ni = 0; ni < 8; ni++) {
                int col = kt*64 + ni*8 + 2*gc;
                if (col     > qrow0)     sc[ni][0] = -1e30f;
                if (col + 1 > qrow0)     sc[ni][1] = -1e30f;
                if (col     > qrow0 + 8) sc[ni][2] = -1e30f;
                if (col + 1 > qrow0 + 8) sc[ni][3] = -1e30f;
            }
        }

        float mx0 = -INFINITY, mx1 = -INFINITY;
#pragma unroll
        for (int ni = 0; ni < 8; ni++) {
            mx0 = fmaxf(mx0, fmaxf(sc[ni][0], sc[ni][1]));
            mx1 = fmaxf(mx1, fmaxf(sc[ni][2], sc[ni][3]));
        }
        mx0 = fmaxf(mx0, __shfl_xor_sync(0xffffffffu, mx0, 1));
        mx0 = fmaxf(mx0, __shfl_xor_sync(0xffffffffu, mx0, 2));
        mx1 = fmaxf(mx1, __shfl_xor_sync(0xffffffffu, mx1, 1));
        mx1 = fmaxf(mx1, __shfl_xor_sync(0xffffffffu, mx1, 2));
        float mn0 = fmaxf(m0, mx0), mn1 = fmaxf(m1, mx1);
        float al0 = ex2(m0 - mn0), al1 = ex2(m1 - mn1);
        m0 = mn0; m1 = mn1;

        const int pp = (gc < 2) ? 4*gc : 4*gc - 7;
        float* pr0 = &QP[arow*FSTR];
        float* pr1 = &QP[(arow+8)*FSTR];
        float s0 = 0.f, s1 = 0.f;
#pragma unroll
        for (int ni = 0; ni < 8; ni++) {
            float p00 = ex2(sc[ni][0] - mn0);
            float p01 = ex2(sc[ni][1] - mn0);
            float p10 = ex2(sc[ni][2] - mn1);
            float p11 = ex2(sc[ni][3] - mn1);
            s0 += p00 + p01;
            s1 += p10 + p11;
            int c = ni*8 + pp;
            pr0[c]   = p00;  pr0[c+2] = p01;
            pr1[c]   = p10;  pr1[c+2] = p11;
        }
        s0 += __shfl_xor_sync(0xffffffffu, s0, 1);
        s0 += __shfl_xor_sync(0xffffffffu, s0, 2);
        s1 += __shfl_xor_sync(0xffffffffu, s1, 1);
        s1 += __shfl_xor_sync(0xffffffffu, s1, 2);
        l0 = l0 * al0 + s0;
        l1 = l1 * al1 + s1;

#pragma unroll
        for (int ni = 0; ni < 8; ni++) {
            o[ni][0] *= al0; o[ni][1] *= al0;
            o[ni][2] *= al1; o[ni][3] *= al1;
        }
        __syncwarp();

        // O += P V : a-frags uint2 from permuted P; b-frags uint2 from transposed V
#pragma unroll
        for (int ks = 0; ks < 8; ks++) {
            uint2 plo = *(const uint2*)&QP[arow*FSTR + ks*8 + 2*gc];
            uint2 phi = *(const uint2*)&QP[(arow+8)*FSTR + ks*8 + 2*gc];
            unsigned pa[4] = { plo.x, phi.x, plo.y, phi.y };
#pragma unroll
            for (int ni = 0; ni < 8; ni++) {
                uint2 bb = *(const uint2*)&Vst[(ni*8 + gr)*FSTR + ks*8 + 2*gc];
                unsigned b[2] = { bb.x, bb.y };
                mma_tf32(o[ni], pa, b);
            }
        }
    }

    float inv0 = 1.f / l0, inv1 = 1.f / l1;
    const int b = bh / NH_, h = bh % NH_;
    const int srow0 = qt*128 + wid*16 + gr;
#pragma unroll
    for (int ni = 0; ni < 8; ni++) {
        int col = h*64 + ni*8 + 2*gc;
        *(float2*)(g_attn + (size_t)(b*S_ + srow0) * H_ + col) =
            make_float2(__uint_as_float(f2tf32(o[ni][0]*inv0)),
                        __uint_as_float(f2tf32(o[ni][1]*inv0)));
        *(float2*)(g_attn + (size_t)(b*S_ + srow0 + 8) * H_ + col) =
            make_float2(__uint_as_float(f2tf32(o[ni][2]*inv1)),
                        __uint_as_float(f2tf32(o[ni][3]*inv1)));
    }
}

// ---------------- launch --------------------------------------------------------------
extern "C" void kernel_launch(void* const* d_in, const int* in_sizes, int n_in,
                              void* d_out, int out_size) {
    (void)in_sizes; (void)n_in; (void)out_size;
    const float* x       = (const float*)d_in[0];
    const float* ve      = (const float*)d_in[1];
    const float* Wqkv    = (const float*)d_in[2];
    const float* Wo      = (const float*)d_in[3];
    const float* lambdas = (const float*)d_in[4];
    float* out = (float*)d_out;

    void *p_qkv, *p_attn, *p_x32, *p_w1, *p_w2;
    cudaGetSymbolAddress(&p_qkv,  g_qkv);
    cudaGetSymbolAddress(&p_attn, g_attn);
    cudaGetSymbolAddress(&p_x32,  g_x32);
    cudaGetSymbolAddress(&p_w1,   g_w1);
    cudaGetSymbolAddress(&p_w2,   g_w2);

    static bool attr_done = false;
    if (!attr_done) {
        cudaFuncSetAttribute(flash_v8, cudaFuncAttributeMaxDynamicSharedMemorySize,
                             FLASH_SMEM_BYTES);
        cudaFuncSetAttribute(gemm_v8, cudaFuncAttributeMaxDynamicSharedMemorySize,
                             GEMM_SMEM_BYTES);
        attr_done = true;
    }

    // 0) tf32-pre-round GEMM inputs
    cvt_tf32_kernel<<<ROWS_*H_/4/256, 256>>>(x,    (float*)p_x32, ROWS_*H_);
    cvt_tf32_kernel<<<3*H_*H_/4/256,  256>>>(Wqkv, (float*)p_w1,  3*H_*H_);
    cvt_tf32_kernel<<<H_*H_/4/256,    256>>>(Wo,   (float*)p_w2,  H_*H_);
    // 1) qkv = x @ W_qkv^T
    gemm_v8<<<dim3(3*H_/128, ROWS_/128), 256, GEMM_SMEM_BYTES>>>(
        (const float*)p_x32, (const float*)p_w1, (float*)p_qkv, ROWS_, 3*H_, H_);
    // 2) RoPE table
    rope_table_kernel<<<(S_*32 + 255)/256, 256>>>();
    // 3) prep
    prep_kernel<<<(B_*S_*NH_*32 + 255)/256, 256>>>(ve, lambdas);
    // 3b) V transpose + s-permute
    vtrans_kernel<<<dim3(S_/64, B_*NH_), 256>>>();
    // 4) causal flash attention
    flash_v8<<<dim3(S_/128, B_*NH_), 256, FLASH_SMEM_BYTES>>>();
    // 5) out = attn @ W_o^T
    gemm_v8<<<dim3(H_/128, ROWS_/128), 256, GEMM_SMEM_BYTES>>>(
        (const float*)p_attn, (const float*)p_w2, out, ROWS_, H_, H_);
}

// round 15
// speedup vs baseline: 1.1801x; 1.0495x over previous
#include <cuda_runtime.h>
#include <cuda_bf16.h>
#include <math.h>
#include <stdint.h>

// Problem constants
#define B_  2
#define S_  2048
#define H_  1024
#define NH_ 16
#define D_  64
#define ROWS_ (B_*S_)        // 4096
#define EPS_ 1.1920929e-07f
#define QSCALE_ (0.125f * 1.4426950408889634f)   // (1/sqrt(D)) * log2(e)

// ---------------- scratch -------------------------------------------------------------
__device__ float g_qkv[(size_t)ROWS_ * 3 * H_];   // natural
__device__ float g_q[(size_t)B_*NH_*S_*D_];       // d-permuted (flash frag layout)
__device__ float g_k[(size_t)B_*NH_*S_*D_];       // d-permuted
__device__ float g_v[(size_t)B_*NH_*S_*D_];       // natural
__device__ float g_attn[(size_t)ROWS_ * H_];      // natural, tf32-rounded
__device__ float g_x32[(size_t)ROWS_ * H_];       // tf32 natural
__device__ float g_w1[(size_t)3*H_ * H_];         // tf32 natural
__device__ float g_w2[(size_t)H_ * H_];           // tf32 natural
__device__ float g_cos[S_*32];
__device__ float g_sin[S_*32];

// ---------------- helpers -------------------------------------------------------------
__device__ __forceinline__ unsigned f2tf32(float f) {
    unsigned u;
    asm("cvt.rna.tf32.f32 %0, %1;" : "=r"(u) : "f"(f));
    return u;
}
__device__ __forceinline__ float ex2(float x) {
    float r;
    asm("ex2.approx.f32 %0, %1;" : "=f"(r) : "f"(x));
    return r;
}
__device__ __forceinline__ void mma_tf32(float c[4], const unsigned a[4], const unsigned b[2]) {
    asm volatile(
        "mma.sync.aligned.m16n8k8.row.col.f32.tf32.tf32.f32 "
        "{%0,%1,%2,%3}, {%4,%5,%6,%7}, {%8,%9}, {%0,%1,%2,%3};"
        : "+f"(c[0]), "+f"(c[1]), "+f"(c[2]), "+f"(c[3])
        : "r"(a[0]), "r"(a[1]), "r"(a[2]), "r"(a[3]), "r"(b[0]), "r"(b[1]));
}
__device__ __forceinline__ void cp16(unsigned dst, const void* src) {
    asm volatile("cp.async.cg.shared.global [%0], [%1], 16;" :: "r"(dst), "l"(src));
}
__device__ __forceinline__ uint32_t smem_u32(const void* p) {
    return (uint32_t)__cvta_generic_to_shared(p);
}

// ---------------- elementwise tf32 rounding -------------------------------------------
__global__ void cvt_tf32_kernel(const float* __restrict__ in, float* __restrict__ out, int n) {
    int i = (blockIdx.x * blockDim.x + threadIdx.x) * 4;
    if (i >= n) return;
    float4 v = *(const float4*)(in + i);
    float4 o;
    o.x = __uint_as_float(f2tf32(v.x));
    o.y = __uint_as_float(f2tf32(v.y));
    o.z = __uint_as_float(f2tf32(v.z));
    o.w = __uint_as_float(f2tf32(v.w));
    *(float4*)(out + i) = o;
}

// ---------------- RoPE table ----------------------------------------------------------
__global__ void rope_table_kernel() {
    int idx = blockIdx.x * blockDim.x + threadIdx.x;
    if (idx >= S_*32) return;
    int s = idx >> 5, j = idx & 31;
    double invf = pow(1.0e-4, (double)j / 32.0);
    float f = (float)s * (float)invf;
    double sn, cs;
    sincos((double)f, &sn, &cs);
    g_cos[idx] = (float)cs;
    g_sin[idx] = (float)sn;
}

// ---------------- tf32 GEMM v10: 256x128 tile, 512 thr, 3 stages, 1 barrier/slab ------
// C[M,N] = A[M,K] * B[N,K]^T, inputs tf32-pre-rounded natural layout.
// L2 traffic: M*K*(N/128) + N*K*(M/256)  (25% less than 128x128).
// 16 warps = 4m x 4n, warp tile 64x32 (4 m-mma x 4 n-mma). GP=36 pad (conflict-free).
#define GP 36
#define GA_SLAB (256*GP)                       // A words per stage
#define GB_SLAB (128*GP)                       // B words per stage
#define GST_SLAB (GA_SLAB + GB_SLAB)
#define GEMM_SMEM_BYTES (3*GST_SLAB*4)         // 165888 -> 1 CTA/SM

__global__ __launch_bounds__(512, 1)
void gemm_v10(const float* __restrict__ A, const float* __restrict__ Bm,
              float* __restrict__ C, int M, int N, int K) {
    extern __shared__ unsigned smg[];
    // stage s: A at s*GST_SLAB, B at s*GST_SLAB + GA_SLAB
    const int tid  = threadIdx.x;
    const int lane = tid & 31;
    const int wid  = tid >> 5;
    const int gr   = lane >> 2;
    const int gc   = lane & 3;
    const int bm = blockIdx.y * 256;
    const int bn = blockIdx.x * 128;
    const int wm = (wid >> 2) * 64;            // 0,64,128,192
    const int wn = (wid & 3) * 32;             // 0,32,64,96

    const unsigned sm_u32 = smem_u32(smg);

    auto load_slab = [&](int t, int s) {
        const int k0 = t << 5;
        const unsigned base = sm_u32 + (unsigned)(s*GST_SLAB*4);
        // A: 2048 chunks (256 rows x 8), 4 per thread
#pragma unroll
        for (int i = 0; i < 4; i++) {
            int ca = tid + i*512;
            int r = ca >> 3, c = ca & 7;
            cp16(base + (unsigned)((r*GP + c*4) * 4),
                 A + (size_t)(bm + r) * K + k0 + c*4);
        }
        // B: 1024 chunks (128 rows x 8), 2 per thread
#pragma unroll
        for (int i = 0; i < 2; i++) {
            int cb = tid + i*512;
            int r = cb >> 3, c = cb & 7;
            cp16(base + (unsigned)((GA_SLAB + r*GP + c*4) * 4),
                 Bm + (size_t)(bn + r) * K + k0 + c*4);
        }
        asm volatile("cp.async.commit_group;");
    };

    float acc[4][4][4];
#pragma unroll
    for (int mi = 0; mi < 4; mi++)
#pragma unroll
        for (int ni = 0; ni < 4; ni++)
#pragma unroll
            for (int j = 0; j < 4; j++) acc[mi][ni][j] = 0.f;

    const int T = K >> 5;                      // 32 slabs
    load_slab(0, 0);

    for (int t = 0; t < T; t++) {
        const int cur = t % 3;
        if (t + 1 < T) {
            load_slab(t + 1, (t + 1) % 3);
            asm volatile("cp.async.wait_group 1;");
        } else {
            asm volatile("cp.async.wait_group 0;");
        }
        __syncthreads();

        const unsigned* Ab = smg + cur*GST_SLAB;
        const unsigned* Bb = Ab + GA_SLAB;
#pragma unroll
        for (int ks = 0; ks < 4; ks++) {
            const int kb = ks * 8;
            unsigned a[4][4];
#pragma unroll
            for (int mi = 0; mi < 4; mi++) {
                const unsigned* ap = &Ab[(wm + mi*16 + gr)*GP + kb + gc];
                a[mi][0] = ap[0];
                a[mi][1] = ap[8*GP];
                a[mi][2] = ap[4];
                a[mi][3] = ap[8*GP + 4];
            }
#pragma unroll
            for (int ni = 0; ni < 4; ni++) {
                const unsigned* bp = &Bb[(wn + ni*8 + gr)*GP + kb + gc];
                unsigned b[2] = { bp[0], bp[4] };
#pragma unroll
                for (int mi = 0; mi < 4; mi++)
                    mma_tf32(acc[mi][ni], a[mi], b);
            }
        }
    }

#pragma unroll
    for (int mi = 0; mi < 4; mi++) {
        int m0 = bm + wm + mi*16 + gr;
#pragma unroll
        for (int ni = 0; ni < 4; ni++) {
            int n = bn + wn + ni*8 + 2*gc;
            *(float2*)(C + (size_t)m0 * N + n)       = make_float2(acc[mi][ni][0], acc[mi][ni][1]);
            *(float2*)(C + (size_t)(m0 + 8) * N + n) = make_float2(acc[mi][ni][2], acc[mi][ni][3]);
        }
    }
}

// ---------------- prep (unchanged from R12) -------------------------------------------
__global__ void prep_kernel(const float* __restrict__ ve, const float* __restrict__ lambdas) {
    int gtid = blockIdx.x * blockDim.x + threadIdx.x;
    int warp = gtid >> 5;
    int lane = gtid & 31;
    if (warp >= B_*S_*NH_) return;
    int h = warp % NH_;
    int s = (warp / NH_) % S_;
    int b = warp / (NH_ * S_);

    const float* row = g_qkv + (size_t)(b*S_ + s) * (3*H_);
    float q1 = row[h*64 + lane],          q2 = row[h*64 + 32 + lane];
    float k1 = row[H_ + h*64 + lane],     k2 = row[H_ + h*64 + 32 + lane];
    float v1 = row[2*H_ + h*64 + lane],   v2 = row[2*H_ + h*64 + 32 + lane];

    float sq = q1*q1 + q2*q2;
    float sk = k1*k1 + k2*k2;
#pragma unroll
    for (int o = 16; o; o >>= 1) {
        sq += __shfl_xor_sync(0xffffffffu, sq, o);
        sk += __shfl_xor_sync(0xffffffffu, sk, o);
    }
    float rq = rsqrtf(sq * (1.f/64.f) + EPS_);
    float rk = rsqrtf(sk * (1.f/64.f) + EPS_);
    q1 *= rq; q2 *= rq; k1 *= rk; k2 *= rk;

    float c  = g_cos[s*32 + lane];
    float sn = g_sin[s*32 + lane];
    float qo1 = (q1*c + q2*sn) * QSCALE_;
    float qo2 = (q2*c - q1*sn) * QSCALE_;
    float ko1 = k1*c + k2*sn, ko2 = k2*c - k1*sn;

    float l0 = lambdas[0], l1 = lambdas[1];
    const float* verow = ve + (size_t)(b*S_ + s) * H_ + h*64;
    float vo1 = l0*v1 + l1*verow[lane];
    float vo2 = l0*v2 + l1*verow[32 + lane];

    size_t ob = ((size_t)(b*NH_ + h) * S_ + s) * 64;
    int j    = lane & 7;
    int pbase = (lane >> 3) * 8 + 2*(j & 3) + (j >> 2);
    g_q[ob + pbase]      = __uint_as_float(f2tf32(qo1));
    g_q[ob + pbase + 32] = __uint_as_float(f2tf32(qo2));
    g_k[ob + pbase]      = __uint_as_float(f2tf32(ko1));
    g_k[ob + pbase + 32] = __uint_as_float(f2tf32(ko2));
    g_v[ob + lane]       = __uint_as_float(f2tf32(vo1));
    g_v[ob + lane + 32]  = __uint_as_float(f2tf32(vo2));
}

// ---------------- flash attention v6 (unchanged R12 winner) ---------------------------
#define FSTR 72
#define STAGE_W (64*FSTR)
#define FLASH_SMEM_BYTES ((128*FSTR + 4*STAGE_W)*4)   // 110592

__global__ __launch_bounds__(256, 2)
void flash_v6() {
    extern __shared__ float sm[];
    float* QP = sm;
    float* Ks = sm + 128*FSTR;
    float* Vs = Ks + 2*STAGE_W;

    const int tid  = threadIdx.x;
    const int lane = tid & 31;
    const int wid  = tid >> 5;
    const int gr   = lane >> 2;
    const int gc   = lane & 3;
    const int qt   = gridDim.x - 1 - blockIdx.x;
    const int bh   = blockIdx.y;
    const int arow = wid*16 + gr;

    const unsigned ks_u32 = smem_u32(Ks);
    const unsigned vs_u32 = smem_u32(Vs);
    const float* Kbase = g_k + (size_t)bh * S_ * 64;
    const float* Vbase = g_v + (size_t)bh * S_ * 64;
    const int ktmax = 2*qt + 1;

    const int cr = tid >> 4;
    const int cc = (tid & 15) << 2;

    {
#pragma unroll
        for (int j = 0; j < 4; j++) {
            int r = cr + j*16;
            unsigned off = (unsigned)((r*FSTR + cc) * 4);
            cp16(ks_u32 + off, Kbase + r*64 + cc);
            cp16(vs_u32 + off, Vbase + r*64 + cc);
        }
        asm volatile("cp.async.commit_group;");
    }

    const float* Qg = g_q + ((size_t)bh * S_ + qt*128) * 64;
    for (int i = tid; i < 2048; i += 256) {
        int r = i >> 4, dc = (i & 15) << 2;
        *(float4*)&QP[r*FSTR + dc] = *(const float4*)(Qg + r*64 + dc);
    }
    __syncthreads();

    unsigned qa[8][4];
#pragma unroll
    for (int ks = 0; ks < 8; ks++) {
        uint2 lo = *(const uint2*)&QP[arow*FSTR + ks*8 + 2*gc];
        uint2 hi = *(const uint2*)&QP[(arow+8)*FSTR + ks*8 + 2*gc];
        qa[ks][0] = lo.x; qa[ks][1] = hi.x; qa[ks][2] = lo.y; qa[ks][3] = hi.y;
    }

    float o[8][4];
#pragma unroll
    for (int ni = 0; ni < 8; ni++)
#pragma unroll
        for (int j = 0; j < 4; j++) o[ni][j] = 0.f;
    float m0 = -INFINITY, m1 = -INFINITY, l0 = 0.f, l1 = 0.f;

    for (int kt = 0; kt <= ktmax; kt++) {
        const int cur = kt & 1;
        __syncthreads();

        if (kt < ktmax) {
            const int nst = cur ^ 1;
            const float* Kg = Kbase + (size_t)(kt+1)*64*64;
            const float* Vg = Vbase + (size_t)(kt+1)*64*64;
            unsigned kd = ks_u32 + (unsigned)(nst*STAGE_W*4);
            unsigned vd = vs_u32 + (unsigned)(nst*STAGE_W*4);
#pragma unroll
            for (int j = 0; j < 4; j++) {
                int r = cr + j*16;
                unsigned off = (unsigned)((r*FSTR + cc) * 4);
                cp16(kd + off, Kg + r*64 + cc);
                cp16(vd + off, Vg + r*64 + cc);
            }
            asm volatile("cp.async.commit_group;");
            asm volatile("cp.async.wait_group 1;");
        } else {
            asm volatile("cp.async.wait_group 0;");
        }
        __syncthreads();

        const float* Kst = Ks + cur*STAGE_W;
        const float* Vst = Vs + cur*STAGE_W;

        float sc[8][4];
#pragma unroll
        for (int ni = 0; ni < 8; ni++)
#pragma unroll
            for (int j = 0; j < 4; j++) sc[ni][j] = 0.f;
#pragma unroll
        for (int ks = 0; ks < 8; ks++) {
#pragma unroll
            for (int ni = 0; ni < 8; ni++) {
                uint2 bb = *(const uint2*)&Kst[(ni*8 + gr)*FSTR + ks*8 + 2*gc];
                unsigned b[2] = { bb.x, bb.y };
                mma_tf32(sc[ni], qa[ks], b);
            }
        }

        const int qrow0 = qt*128 + wid*16 + gr;
        if (kt >= 2*qt) {
#pragma unroll
            for (int ni = 0; ni < 8; ni++) {
                int col = kt*64 + ni*8 + 2*gc;
                if (col     > qrow0)     sc[ni][0] = -1e30f;
                if (col + 1 > qrow0)     sc[ni][1] = -1e30f;
                if (col     > qrow0 + 8) sc[ni][2] = -1e30f;
                if (col + 1 > qrow0 + 8) sc[ni][3] = -1e30f;
            }
        }

        float mx0 = -INFINITY, mx1 = -INFINITY;
#pragma unroll
        for (int ni = 0; ni < 8; ni++) {
            mx0 = fmaxf(mx0, fmaxf(sc[ni][0], sc[ni][1]));
            mx1 = fmaxf(mx1, fmaxf(sc[ni][2], sc[ni][3]));
        }
        mx0 = fmaxf(mx0, __shfl_xor_sync(0xffffffffu, mx0, 1));
        mx0 = fmaxf(mx0, __shfl_xor_sync(0xffffffffu, mx0, 2));
        mx1 = fmaxf(mx1, __shfl_xor_sync(0xffffffffu, mx1, 1));
        mx1 = fmaxf(mx1, __shfl_xor_sync(0xffffffffu, mx1, 2));
        float mn0 = fmaxf(m0, mx0), mn1 = fmaxf(m1, mx1);
        float al0 = ex2(m0 - mn0), al1 = ex2(m1 - mn1);
        m0 = mn0; m1 = mn1;

        const int pp = (gc < 2) ? 4*gc : 4*gc - 7;
        float* pr0 = &QP[arow*FSTR];
        float* pr1 = &QP[(arow+8)*FSTR];
        float s0 = 0.f, s1 = 0.f;
#pragma unroll
        for (int ni = 0; ni < 8; ni++) {
            float p00 = ex2(sc[ni][0] - mn0);
            float p01 = ex2(sc[ni][1] - mn0);
            float p10 = ex2(sc[ni][2] - mn1);
            float p11 = ex2(sc[ni][3] - mn1);
            s0 += p00 + p01;
            s1 += p10 + p11;
            int c = ni*8 + pp;
            pr0[c]   = p00;  pr0[c+2] = p01;
            pr1[c]   = p10;  pr1[c+2] = p11;
        }
        s0 += __shfl_xor_sync(0xffffffffu, s0, 1);
        s0 += __shfl_xor_sync(0xffffffffu, s0, 2);
        s1 += __shfl_xor_sync(0xffffffffu, s1, 1);
        s1 += __shfl_xor_sync(0xffffffffu, s1, 2);
        l0 = l0 * al0 + s0;
        l1 = l1 * al1 + s1;

#pragma unroll
        for (int ni = 0; ni < 8; ni++) {
            o[ni][0] *= al0; o[ni][1] *= al0;
            o[ni][2] *= al1; o[ni][3] *= al1;
        }
        __syncwarp();

#pragma unroll
        for (int ks = 0; ks < 8; ks++) {
            uint2 plo = *(const uint2*)&QP[arow*FSTR + ks*8 + 2*gc];
            uint2 phi = *(const uint2*)&QP[(arow+8)*FSTR + ks*8 + 2*gc];
            unsigned pa[4] = { plo.x, phi.x, plo.y, phi.y };
#pragma unroll
            for (int ni = 0; ni < 8; ni++) {
                unsigned b[2] = { __float_as_uint(Vst[(ks*8 + gc)*FSTR + ni*8 + gr]),
                                  __float_as_uint(Vst[(ks*8 + gc + 4)*FSTR + ni*8 + gr]) };
                mma_tf32(o[ni], pa, b);
            }
        }
    }

    float inv0 = 1.f / l0, inv1 = 1.f / l1;
    const int b = bh / NH_, h = bh % NH_;
    const int srow0 = qt*128 + wid*16 + gr;
#pragma unroll
    for (int ni = 0; ni < 8; ni++) {
        int col = h*64 + ni*8 + 2*gc;
        *(float2*)(g_attn + (size_t)(b*S_ + srow0) * H_ + col) =
            make_float2(__uint_as_float(f2tf32(o[ni][0]*inv0)),
                        __uint_as_float(f2tf32(o[ni][1]*inv0)));
        *(float2*)(g_attn + (size_t)(b*S_ + srow0 + 8) * H_ + col) =
            make_float2(__uint_as_float(f2tf32(o[ni][2]*inv1)),
                        __uint_as_float(f2tf32(o[ni][3]*inv1)));
    }
}

// ---------------- launch --------------------------------------------------------------
extern "C" void kernel_launch(void* const* d_in, const int* in_sizes, int n_in,
                              void* d_out, int out_size) {
    (void)in_sizes; (void)n_in; (void)out_size;
    const float* x       = (const float*)d_in[0];
    const float* ve      = (const float*)d_in[1];
    const float* Wqkv    = (const float*)d_in[2];
    const float* Wo      = (const float*)d_in[3];
    const float* lambdas = (const float*)d_in[4];
    float* out = (float*)d_out;

    void *p_qkv, *p_attn, *p_x32, *p_w1, *p_w2;
    cudaGetSymbolAddress(&p_qkv,  g_qkv);
    cudaGetSymbolAddress(&p_attn, g_attn);
    cudaGetSymbolAddress(&p_x32,  g_x32);
    cudaGetSymbolAddress(&p_w1,   g_w1);
    cudaGetSymbolAddress(&p_w2,   g_w2);

    static bool attr_done = false;
    if (!attr_done) {
        cudaFuncSetAttribute(flash_v6, cudaFuncAttributeMaxDynamicSharedMemorySize,
                             FLASH_SMEM_BYTES);
        cudaFuncSetAttribute(gemm_v10, cudaFuncAttributeMaxDynamicSharedMemorySize,
                             GEMM_SMEM_BYTES);
        attr_done = true;
    }

    // 0) tf32-pre-round GEMM inputs
    cvt_tf32_kernel<<<ROWS_*H_/4/256, 256>>>(x,    (float*)p_x32, ROWS_*H_);
    cvt_tf32_kernel<<<3*H_*H_/4/256,  256>>>(Wqkv, (float*)p_w1,  3*H_*H_);
    cvt_tf32_kernel<<<H_*H_/4/256,    256>>>(Wo,   (float*)p_w2,  H_*H_);
    // 1) qkv = x @ W_qkv^T   (256x128 tiles)
    gemm_v10<<<dim3(3*H_/128, ROWS_/256), 512, GEMM_SMEM_BYTES>>>(
        (const float*)p_x32, (const float*)p_w1, (float*)p_qkv, ROWS_, 3*H_, H_);
    // 2) RoPE table
    rope_table_kernel<<<(S_*32 + 255)/256, 256>>>();
    // 3) prep
    prep_kernel<<<(B_*S_*NH_*32 + 255)/256, 256>>>(ve, lambdas);
    // 4) causal flash attention
    flash_v6<<<dim3(S_/128, B_*NH_), 256, FLASH_SMEM_BYTES>>>();
    // 5) out = attn @ W_o^T
    gemm_v10<<<dim3(H_/128, ROWS_/256), 512, GEMM_SMEM_BYTES>>>(
        (const float*)p_attn, (const float*)p_w2, out, ROWS_, H_, H_);
}